// round 3
// baseline (speedup 1.0000x reference)
#include <cuda_runtime.h>

#define BSZ  8
#define CDIM 64
#define NPTS 4096
#define KNN  20
#define OC   64

// ---------------- scratch (device globals; no allocation) ----------------
__device__ float g_sq [BSZ*NPTS];
__device__ float g_u  [BSZ*NPTS*OC];
__device__ float g_v  [BSZ*NPTS*OC];
__device__ int   g_idx[BSZ*NPTS*KNN];
__device__ float g_mxv[BSZ*NPTS*OC];
__device__ float g_mnv[BSZ*NPTS*OC];
__device__ float g_S1[OC];
__device__ float g_S2[OC];
__device__ float g_ga[OC];
__device__ float g_gb[OC];

// ---------------- kernel 0: squared norms + zero stats ----------------
__global__ __launch_bounds__(256) void k_sq(const float* __restrict__ x) {
    const int b = blockIdx.y;
    const int n = blockIdx.x * 256 + threadIdx.x;
    const float* xb = x + (size_t)b * CDIM * NPTS;
    float s = 0.f;
#pragma unroll 8
    for (int c = 0; c < CDIM; ++c) {
        float t = xb[c * NPTS + n];
        s += t * t;
    }
    g_sq[b * NPTS + n] = s;
    if (blockIdx.x == 0 && blockIdx.y == 0 && threadIdx.x < OC) {
        g_S1[threadIdx.x] = 0.f;
        g_S2[threadIdx.x] = 0.f;
    }
}

// ---------------- kernel A: u = W1*x, v = (W2-W1)*x, layout [b][n][o] ---
__global__ __launch_bounds__(256) void k_uv(const float* __restrict__ x,
                                            const float* __restrict__ W) {
    __shared__ float Wc[128 * 64];  // 32KB; later reused as transpose staging
    __shared__ float xt[64 * 32];   // 8KB
    const int b = blockIdx.y, n0 = blockIdx.x * 32;
    const int tx = threadIdx.x, ty = threadIdx.y, tid = ty * 16 + tx;

    for (int i = tid; i < 128 * 64; i += 256) {
        int r = i >> 6, c = i & 63;
        float wv;
        if (r < 64) wv = W[r * 128 + c];
        else        wv = W[(r - 64) * 128 + 64 + c] - W[(r - 64) * 128 + c];
        Wc[i] = wv;
    }
    const float* xb = x + (size_t)b * CDIM * NPTS;
    for (int i = tid; i < 64 * 32; i += 256) {
        int c = i >> 5, nn = i & 31;
        xt[i] = xb[c * NPTS + n0 + nn];
    }
    __syncthreads();

    float acc[8][2] = {};
#pragma unroll 8
    for (int c = 0; c < 64; ++c) {
        float2 bv = *(const float2*)&xt[c * 32 + tx * 2];
#pragma unroll
        for (int i = 0; i < 8; ++i) {
            float a = Wc[(ty * 8 + i) * 64 + c];
            acc[i][0] += a * bv.x;
            acc[i][1] += a * bv.y;
        }
    }
    __syncthreads();

    // stage + coalesced store: u (rows 0..63 of Wcat)
    if (ty < 8) {
#pragma unroll
        for (int i = 0; i < 8; ++i) {
            Wc[(tx * 2 + 0) * 65 + ty * 8 + i] = acc[i][0];
            Wc[(tx * 2 + 1) * 65 + ty * 8 + i] = acc[i][1];
        }
    }
    __syncthreads();
    {
        float* dst = g_u + ((size_t)b * NPTS + n0) * OC;
        for (int i = tid; i < 32 * 64; i += 256) {
            int nn = i >> 6, oo = i & 63;
            dst[i] = Wc[nn * 65 + oo];
        }
    }
    __syncthreads();
    // stage + store: v (rows 64..127)
    if (ty >= 8) {
#pragma unroll
        for (int i = 0; i < 8; ++i) {
            Wc[(tx * 2 + 0) * 65 + (ty - 8) * 8 + i] = acc[i][0];
            Wc[(tx * 2 + 1) * 65 + (ty - 8) * 8 + i] = acc[i][1];
        }
    }
    __syncthreads();
    {
        float* dst = g_v + ((size_t)b * NPTS + n0) * OC;
        for (int i = tid; i < 32 * 64; i += 256) {
            int nn = i >> 6, oo = i & 63;
            dst[i] = Wc[nn * 65 + oo];
        }
    }
}

// ---------------- kernel B: fused Gram + top-K selection ----------------
__device__ __forceinline__ void insert_cand(float k, int m, float& tk, int& ti,
                                            float& thr, int& minl, int lane) {
    unsigned bal = __ballot_sync(0xffffffffu, k > thr);
    while (bal) {
        int src = __ffs(bal) - 1;
        bal &= bal - 1;
        float ck = __shfl_sync(0xffffffffu, k, src);
        int   cm = __shfl_sync(0xffffffffu, m, src);
        if (ck > thr) {                  // re-check: thr may have risen
            if (lane == minl) { tk = ck; ti = cm; }
            float mv = (lane < KNN) ? tk : 3.4e38f;
            int   ml = lane;
#pragma unroll
            for (int off = 16; off; off >>= 1) {
                float ov = __shfl_xor_sync(0xffffffffu, mv, off);
                int   ol = __shfl_xor_sync(0xffffffffu, ml, off);
                if (ov < mv || (ov == mv && ol < ml)) { mv = ov; ml = ol; }
            }
            thr = mv; minl = ml;         // uniform across warp (tie-broken by lane)
        }
    }
}

__global__ __launch_bounds__(256) void k_knn(const float* __restrict__ x) {
    __shared__ float qs[64 * 64];   // query tile  [c][q]
    __shared__ float Bs[64 * 64];   // cand tile   [c][m]  (aliased as keys [q][m])
    __shared__ float sqs[64];
    const int b = blockIdx.y;
    const int q0 = blockIdx.x * 64;
    const int tx = threadIdx.x, ty = threadIdx.y;
    const int tid = ty * 16 + tx, lane = tid & 31, warp = tid >> 5;
    const float* xb = x + (size_t)b * CDIM * NPTS;

    for (int i = tid; i < 64 * 64; i += 256) {
        int c = i >> 6, qq = i & 63;
        qs[i] = xb[c * NPTS + q0 + qq];
    }

    float tk[8], thr[8];
    int   ti[8], minl[8];
#pragma unroll
    for (int r = 0; r < 8; ++r) {
        tk[r] = -3.4e38f; ti[r] = 0; thr[r] = -3.4e38f; minl[r] = 0;
    }

    for (int t = 0; t < NPTS / 64; ++t) {
        const int m0 = t * 64;
        __syncthreads();   // covers qs init (t==0) and previous selection reads of Bs
        for (int i = tid; i < 64 * 64; i += 256) {
            int c = i >> 6, mm = i & 63;
            Bs[i] = xb[c * NPTS + m0 + mm];
        }
        if (tid < 64) sqs[tid] = g_sq[b * NPTS + m0 + tid];
        __syncthreads();

        float acc[4][4] = {};
#pragma unroll 8
        for (int c = 0; c < 64; ++c) {
            float4 av = *(const float4*)&qs[c * 64 + ty * 4];
            float4 bv = *(const float4*)&Bs[c * 64 + tx * 4];
            acc[0][0] += av.x * bv.x; acc[0][1] += av.x * bv.y;
            acc[0][2] += av.x * bv.z; acc[0][3] += av.x * bv.w;
            acc[1][0] += av.y * bv.x; acc[1][1] += av.y * bv.y;
            acc[1][2] += av.y * bv.z; acc[1][3] += av.y * bv.w;
            acc[2][0] += av.z * bv.x; acc[2][1] += av.z * bv.y;
            acc[2][2] += av.z * bv.z; acc[2][3] += av.z * bv.w;
            acc[3][0] += av.w * bv.x; acc[3][1] += av.w * bv.y;
            acc[3][2] += av.w * bv.z; acc[3][3] += av.w * bv.w;
        }
        __syncthreads();   // everyone done reading Bs -> safe to overwrite with keys
        float4 sv = *(const float4*)&sqs[tx * 4];
#pragma unroll
        for (int i = 0; i < 4; ++i) {
            float4 kv;
            kv.x = 2.f * acc[i][0] - sv.x;
            kv.y = 2.f * acc[i][1] - sv.y;
            kv.z = 2.f * acc[i][2] - sv.z;
            kv.w = 2.f * acc[i][3] - sv.w;
            *(float4*)&Bs[(ty * 4 + i) * 64 + tx * 4] = kv;
        }
        __syncthreads();
        // selection: warp w owns rows 8w..8w+7
#pragma unroll
        for (int r = 0; r < 8; ++r) {
            int qrow = warp * 8 + r;
            float k0 = Bs[qrow * 64 + lane];
            float k1 = Bs[qrow * 64 + 32 + lane];
            insert_cand(k0, m0 + lane,      tk[r], ti[r], thr[r], minl[r], lane);
            insert_cand(k1, m0 + 32 + lane, tk[r], ti[r], thr[r], minl[r], lane);
        }
    }
    if (lane < KNN) {
#pragma unroll
        for (int r = 0; r < 8; ++r)
            g_idx[((size_t)b * NPTS + q0 + warp * 8 + r) * KNN + lane] = ti[r];
    }
}

// ---------------- kernel C: one gather pass: max/min + BN stats ----------
__global__ __launch_bounds__(256) void k_gather() {
    __shared__ int   sidx[4][KNN];
    __shared__ float red[2][4][64];
    const int o = threadIdx.x;    // channel
    const int py = threadIdx.y;   // point within group of 4
    const int tid = py * 64 + o;
    const int b = blockIdx.y;
    const int n0 = blockIdx.x * 64;
    const float* ub = g_u + (size_t)b * NPTS * OC;
    float s1 = 0.f, s2 = 0.f;

    for (int it = 0; it < 16; ++it) {
        __syncthreads();
        if (tid < 4 * KNN) {
            int g = tid / KNN, j = tid % KNN;
            sidx[g][j] = g_idx[((size_t)b * NPTS + n0 + it * 4 + g) * KNN + j];
        }
        __syncthreads();
        const int n = n0 + it * 4 + py;
        float s = 0.f, q = 0.f, mx = -3.4e38f, mn = 3.4e38f;
#pragma unroll
        for (int j = 0; j < KNN; ++j) {
            float val = ub[(size_t)sidx[py][j] * OC + o];
            s += val; q += val * val;
            mx = fmaxf(mx, val); mn = fminf(mn, val);
        }
        const size_t off = ((size_t)b * NPTS + n) * OC + o;
        float vv = g_v[off];
        g_mxv[off] = mx + vv;
        g_mnv[off] = mn + vv;
        s1 += (float)KNN * vv + s;
        s2 += (float)KNN * vv * vv + 2.f * vv * s + q;
    }
    red[0][py][o] = s1;
    red[1][py][o] = s2;
    __syncthreads();
    if (py == 0) {
        float a = red[0][0][o] + red[0][1][o] + red[0][2][o] + red[0][3][o];
        float c = red[1][0][o] + red[1][1][o] + red[1][2][o] + red[1][3][o];
        atomicAdd(&g_S1[o], a);
        atomicAdd(&g_S2[o], c);
    }
}

// ---------------- kernel D: finalize BN affine coefficients --------------
__global__ void k_finalize(const float* __restrict__ gamma,
                           const float* __restrict__ beta) {
    int o = threadIdx.x;
    const float M = (float)BSZ * (float)NPTS * (float)KNN;
    float mean = g_S1[o] / M;
    float var  = g_S2[o] / M - mean * mean;
    float a = gamma[o] * rsqrtf(var + 1e-5f);
    g_ga[o] = a;
    g_gb[o] = beta[o] - mean * a;
}

// ---------------- kernel E: affine + LeakyReLU + transpose to [b][o][n] --
__global__ __launch_bounds__(256) void k_out(float* __restrict__ out) {
    __shared__ float tile[64][65];
    const int o = threadIdx.x, ty = threadIdx.y;
    const int b = blockIdx.y, n0 = blockIdx.x * 64;
    const float a = g_ga[o], bc = g_gb[o];
#pragma unroll
    for (int it = 0; it < 16; ++it) {
        int nl = it * 4 + ty;
        size_t off = ((size_t)b * NPTS + n0 + nl) * OC + o;
        float raw = (a >= 0.f) ? g_mxv[off] : g_mnv[off];
        float val = fmaf(a, raw, bc);
        tile[nl][o] = (val >= 0.f) ? val : 0.2f * val;
    }
    __syncthreads();
#pragma unroll
    for (int it = 0; it < 16; ++it) {
        int oo = it * 4 + ty;
        out[((size_t)b * OC + oo) * NPTS + n0 + o] = tile[o][oo];
    }
}

// ---------------- launch ----------------
extern "C" void kernel_launch(void* const* d_in, const int* in_sizes, int n_in,
                              void* d_out, int out_size) {
    const float* x     = (const float*)d_in[0];
    const float* W     = (const float*)d_in[1];
    const float* gamma = (const float*)d_in[2];
    const float* beta  = (const float*)d_in[3];
    float* out = (float*)d_out;

    k_sq      <<<dim3(NPTS / 256, BSZ), 256>>>(x);
    k_uv      <<<dim3(NPTS / 32,  BSZ), dim3(16, 16)>>>(x, W);
    k_knn     <<<dim3(NPTS / 64,  BSZ), dim3(16, 16)>>>(x);
    k_gather  <<<dim3(NPTS / 64,  BSZ), dim3(64, 4)>>>();
    k_finalize<<<1, 64>>>(gamma, beta);
    k_out     <<<dim3(NPTS / 64,  BSZ), dim3(64, 4)>>>(out);
}

// round 6
// speedup vs baseline: 1.2341x; 1.2341x over previous
#include <cuda_runtime.h>

#define BSZ  8
#define CDIM 64
#define NPTS 4096
#define KNN  20
#define OC   64

// ---------------- scratch (device globals; no allocation) ----------------
__device__ float g_sq [BSZ*NPTS];
__device__ float g_u  [BSZ*NPTS*OC];
__device__ float g_v  [BSZ*NPTS*OC];
__device__ int   g_idx[BSZ*NPTS*KNN];
__device__ float g_mxv[BSZ*NPTS*OC];
__device__ float g_mnv[BSZ*NPTS*OC];
__device__ float g_S1[OC];
__device__ float g_S2[OC];
__device__ float g_ga[OC];
__device__ float g_gb[OC];

// packed fp32x2 helpers (FFMA2 only reachable via PTX)
#define FMA2(acc, a, b) \
    asm("fma.rn.f32x2 %0, %1, %2, %0;" : "+l"(acc) : "l"(a), "l"(b))
#define DUP2(dst, f) \
    asm("mov.b64 %0, {%1, %1};" : "=l"(dst) : "f"(f))
#define UNPK2(lo, hi, src) \
    asm("mov.b64 {%0, %1}, %2;" : "=f"(lo), "=f"(hi) : "l"(src))

// ---------------- kernel 0: squared norms + zero stats ----------------
__global__ __launch_bounds__(256) void k_sq(const float* __restrict__ x) {
    const int b = blockIdx.y;
    const int n = blockIdx.x * 256 + threadIdx.x;
    const float* xb = x + (size_t)b * CDIM * NPTS;
    float s = 0.f;
#pragma unroll 8
    for (int c = 0; c < CDIM; ++c) {
        float t = xb[c * NPTS + n];
        s += t * t;
    }
    g_sq[b * NPTS + n] = s;
    if (blockIdx.x == 0 && blockIdx.y == 0 && threadIdx.x < OC) {
        g_S1[threadIdx.x] = 0.f;
        g_S2[threadIdx.x] = 0.f;
    }
}

// ---------------- kernel A: u = W1*x, v = (W2-W1)*x, layout [b][n][o] ---
__global__ __launch_bounds__(256) void k_uv(const float* __restrict__ x,
                                            const float* __restrict__ W) {
    __shared__ float Wc[128 * 64];
    __shared__ float xt[64 * 32];
    const int b = blockIdx.y, n0 = blockIdx.x * 32;
    const int tx = threadIdx.x, ty = threadIdx.y, tid = ty * 16 + tx;

    for (int i = tid; i < 128 * 64; i += 256) {
        int r = i >> 6, c = i & 63;
        float wv;
        if (r < 64) wv = W[r * 128 + c];
        else        wv = W[(r - 64) * 128 + 64 + c] - W[(r - 64) * 128 + c];
        Wc[i] = wv;
    }
    const float* xb = x + (size_t)b * CDIM * NPTS;
    for (int i = tid; i < 64 * 32; i += 256) {
        int c = i >> 5, nn = i & 31;
        xt[i] = xb[c * NPTS + n0 + nn];
    }
    __syncthreads();

    float acc[8][2] = {};
#pragma unroll 8
    for (int c = 0; c < 64; ++c) {
        float2 bv = *(const float2*)&xt[c * 32 + tx * 2];
#pragma unroll
        for (int i = 0; i < 8; ++i) {
            float a = Wc[(ty * 8 + i) * 64 + c];
            acc[i][0] += a * bv.x;
            acc[i][1] += a * bv.y;
        }
    }
    __syncthreads();

    if (ty < 8) {
#pragma unroll
        for (int i = 0; i < 8; ++i) {
            Wc[(tx * 2 + 0) * 65 + ty * 8 + i] = acc[i][0];
            Wc[(tx * 2 + 1) * 65 + ty * 8 + i] = acc[i][1];
        }
    }
    __syncthreads();
    {
        float* dst = g_u + ((size_t)b * NPTS + n0) * OC;
        for (int i = tid; i < 32 * 64; i += 256) {
            int nn = i >> 6, oo = i & 63;
            dst[i] = Wc[nn * 65 + oo];
        }
    }
    __syncthreads();
    if (ty >= 8) {
#pragma unroll
        for (int i = 0; i < 8; ++i) {
            Wc[(tx * 2 + 0) * 65 + (ty - 8) * 8 + i] = acc[i][0];
            Wc[(tx * 2 + 1) * 65 + (ty - 8) * 8 + i] = acc[i][1];
        }
    }
    __syncthreads();
    {
        float* dst = g_v + ((size_t)b * NPTS + n0) * OC;
        for (int i = tid; i < 32 * 64; i += 256) {
            int nn = i >> 6, oo = i & 63;
            dst[i] = Wc[nn * 65 + oo];
        }
    }
}

// ---------------- kernel B: fused Gram (FFMA2) + top-K selection --------
__device__ __forceinline__ void insert_cand(float k, int m, float& tk, int& ti,
                                            float& thr, int& minl, int lane) {
    unsigned bal = __ballot_sync(0xffffffffu, k > thr);
    while (bal) {
        int src = __ffs(bal) - 1;
        bal &= bal - 1;
        float ck = __shfl_sync(0xffffffffu, k, src);
        int   cm = __shfl_sync(0xffffffffu, m, src);
        if (ck > thr) {                  // re-check: thr may have risen
            if (lane == minl) { tk = ck; ti = cm; }
            float mv = (lane < KNN) ? tk : 3.4e38f;
            int   ml = lane;
#pragma unroll
            for (int off = 16; off; off >>= 1) {
                float ov = __shfl_xor_sync(0xffffffffu, mv, off);
                int   ol = __shfl_xor_sync(0xffffffffu, ml, off);
                if (ov < mv || (ov == mv && ol < ml)) { mv = ov; ml = ol; }
            }
            thr = mv; minl = ml;         // uniform across warp
        }
    }
}

#define QTILE 128
#define KPAD  66
// dynamic smem layout (floats): qs[64*128] | Bs[64*64] | keys[128*66] | sqs[64]
#define SM_QS   0
#define SM_BS   (64 * QTILE)
#define SM_KEYS (SM_BS + 64 * 64)
#define SM_SQS  (SM_KEYS + QTILE * KPAD)
#define SM_FLOATS (SM_SQS + 64)
#define SM_BYTES  (SM_FLOATS * 4)

extern __shared__ float sm[];

__global__ __launch_bounds__(256, 2) void k_knn(const float* __restrict__ x) {
    float* qs   = sm + SM_QS;
    float* Bs   = sm + SM_BS;
    float* keys = sm + SM_KEYS;
    float* sqs  = sm + SM_SQS;

    const int b  = blockIdx.y;
    const int q0 = blockIdx.x * QTILE;
    const int tid  = threadIdx.x;
    const int tx   = tid & 15;          // 4 candidate cols
    const int ty   = tid >> 4;          // 8 query rows (0..15)
    const int lane = tid & 31, warp = tid >> 5;
    const float* xb = x + (size_t)b * CDIM * NPTS;

    // load query tile [c][q]
    for (int i = tid; i < 64 * QTILE; i += 256) {
        int c = i >> 7, qq = i & 127;
        qs[i] = xb[c * NPTS + q0 + qq];
    }

    float tk[16], thr[16];
    int   ti[16], minl[16];
#pragma unroll
    for (int r = 0; r < 16; ++r) {
        tk[r] = -3.4e38f; ti[r] = 0; thr[r] = -3.4e38f; minl[r] = 0;
    }

    for (int t = 0; t < NPTS / 64; ++t) {
        const int m0 = t * 64;
        __syncthreads();   // qs ready (t==0) / keys fully consumed (t>0)
        for (int i = tid; i < 64 * 64; i += 256) {
            int c = i >> 6, mm = i & 63;
            Bs[i] = xb[c * NPTS + m0 + mm];
        }
        if (tid < 64) sqs[tid] = g_sq[b * NPTS + m0 + tid];
        __syncthreads();

        // --- 8x4 microtile as 4 row-pairs x 4 cols of f32x2 FFMA2 ---
        unsigned long long acc[4][4];
#pragma unroll
        for (int i = 0; i < 4; ++i)
#pragma unroll
            for (int j = 0; j < 4; ++j) acc[i][j] = 0ull;

#pragma unroll 8
        for (int c = 0; c < 64; ++c) {
            ulonglong2 A0 = *(const ulonglong2*)&qs[c * QTILE + ty * 8];
            ulonglong2 A1 = *(const ulonglong2*)&qs[c * QTILE + ty * 8 + 4];
            float4 bq = *(const float4*)&Bs[c * 64 + tx * 4];
            unsigned long long d0, d1, d2, d3;
            DUP2(d0, bq.x); DUP2(d1, bq.y); DUP2(d2, bq.z); DUP2(d3, bq.w);
            FMA2(acc[0][0], A0.x, d0); FMA2(acc[0][1], A0.x, d1);
            FMA2(acc[0][2], A0.x, d2); FMA2(acc[0][3], A0.x, d3);
            FMA2(acc[1][0], A0.y, d0); FMA2(acc[1][1], A0.y, d1);
            FMA2(acc[1][2], A0.y, d2); FMA2(acc[1][3], A0.y, d3);
            FMA2(acc[2][0], A1.x, d0); FMA2(acc[2][1], A1.x, d1);
            FMA2(acc[2][2], A1.x, d2); FMA2(acc[2][3], A1.x, d3);
            FMA2(acc[3][0], A1.y, d0); FMA2(acc[3][1], A1.y, d1);
            FMA2(acc[3][2], A1.y, d2); FMA2(acc[3][3], A1.y, d3);
        }

        // keys = 2*dot - |m|^2  (identical rounding to previous rounds)
        float4 sv = *(const float4*)&sqs[tx * 4];
#pragma unroll
        for (int i = 0; i < 4; ++i) {
            float lo, hi;
            float* krow0 = &keys[(ty * 8 + 2 * i) * KPAD + tx * 4];
            float* krow1 = krow0 + KPAD;
            UNPK2(lo, hi, acc[i][0]);
            krow0[0] = fmaf(2.f, lo, -sv.x); krow1[0] = fmaf(2.f, hi, -sv.x);
            UNPK2(lo, hi, acc[i][1]);
            krow0[1] = fmaf(2.f, lo, -sv.y); krow1[1] = fmaf(2.f, hi, -sv.y);
            UNPK2(lo, hi, acc[i][2]);
            krow0[2] = fmaf(2.f, lo, -sv.z); krow1[2] = fmaf(2.f, hi, -sv.z);
            UNPK2(lo, hi, acc[i][3]);
            krow0[3] = fmaf(2.f, lo, -sv.w); krow1[3] = fmaf(2.f, hi, -sv.w);
        }
        __syncthreads();

        // selection: warp w owns rows 16w..16w+15
#pragma unroll
        for (int r = 0; r < 16; ++r) {
            const float* krow = &keys[(warp * 16 + r) * KPAD];
            float k0 = krow[lane];
            float k1 = krow[32 + lane];
            insert_cand(k0, m0 + lane,      tk[r], ti[r], thr[r], minl[r], lane);
            insert_cand(k1, m0 + 32 + lane, tk[r], ti[r], thr[r], minl[r], lane);
        }
    }
    if (lane < KNN) {
#pragma unroll
        for (int r = 0; r < 16; ++r)
            g_idx[((size_t)b * NPTS + q0 + warp * 16 + r) * KNN + lane] = ti[r];
    }
}

// ---------------- kernel C: one gather pass: max/min + BN stats ----------
__global__ __launch_bounds__(256) void k_gather() {
    __shared__ int   sidx[4][KNN];
    __shared__ float red[2][4][64];
    const int o = threadIdx.x;
    const int py = threadIdx.y;
    const int tid = py * 64 + o;
    const int b = blockIdx.y;
    const int n0 = blockIdx.x * 64;
    const float* ub = g_u + (size_t)b * NPTS * OC;
    float s1 = 0.f, s2 = 0.f;

    for (int it = 0; it < 16; ++it) {
        __syncthreads();
        if (tid < 4 * KNN) {
            int g = tid / KNN, j = tid % KNN;
            sidx[g][j] = g_idx[((size_t)b * NPTS + n0 + it * 4 + g) * KNN + j];
        }
        __syncthreads();
        const int n = n0 + it * 4 + py;
        float s = 0.f, q = 0.f, mx = -3.4e38f, mn = 3.4e38f;
#pragma unroll
        for (int j = 0; j < KNN; ++j) {
            float val = ub[(size_t)sidx[py][j] * OC + o];
            s += val; q += val * val;
            mx = fmaxf(mx, val); mn = fminf(mn, val);
        }
        const size_t off = ((size_t)b * NPTS + n) * OC + o;
        float vv = g_v[off];
        g_mxv[off] = mx + vv;
        g_mnv[off] = mn + vv;
        s1 += (float)KNN * vv + s;
        s2 += (float)KNN * vv * vv + 2.f * vv * s + q;
    }
    red[0][py][o] = s1;
    red[1][py][o] = s2;
    __syncthreads();
    if (py == 0) {
        float a = red[0][0][o] + red[0][1][o] + red[0][2][o] + red[0][3][o];
        float c = red[1][0][o] + red[1][1][o] + red[1][2][o] + red[1][3][o];
        atomicAdd(&g_S1[o], a);
        atomicAdd(&g_S2[o], c);
    }
}

// ---------------- kernel D: finalize BN affine coefficients --------------
__global__ void k_finalize(const float* __restrict__ gamma,
                           const float* __restrict__ beta) {
    int o = threadIdx.x;
    const float M = (float)BSZ * (float)NPTS * (float)KNN;
    float mean = g_S1[o] / M;
    float var  = g_S2[o] / M - mean * mean;
    float a = gamma[o] * rsqrtf(var + 1e-5f);
    g_ga[o] = a;
    g_gb[o] = beta[o] - mean * a;
}

// ---------------- kernel E: affine + LeakyReLU + transpose to [b][o][n] --
__global__ __launch_bounds__(256) void k_out(float* __restrict__ out) {
    __shared__ float tile[64][65];
    const int o = threadIdx.x, ty = threadIdx.y;
    const int b = blockIdx.y, n0 = blockIdx.x * 64;
    const float a = g_ga[o], bc = g_gb[o];
#pragma unroll
    for (int it = 0; it < 16; ++it) {
        int nl = it * 4 + ty;
        size_t off = ((size_t)b * NPTS + n0 + nl) * OC + o;
        float raw = (a >= 0.f) ? g_mxv[off] : g_mnv[off];
        float val = fmaf(a, raw, bc);
        tile[nl][o] = (val >= 0.f) ? val : 0.2f * val;
    }
    __syncthreads();
#pragma unroll
    for (int it = 0; it < 16; ++it) {
        int oo = it * 4 + ty;
        out[((size_t)b * OC + oo) * NPTS + n0 + o] = tile[o][oo];
    }
}

// ---------------- launch ----------------
extern "C" void kernel_launch(void* const* d_in, const int* in_sizes, int n_in,
                              void* d_out, int out_size) {
    const float* x     = (const float*)d_in[0];
    const float* W     = (const float*)d_in[1];
    const float* gamma = (const float*)d_in[2];
    const float* beta  = (const float*)d_in[3];
    float* out = (float*)d_out;

    cudaFuncSetAttribute(k_knn, cudaFuncAttributeMaxDynamicSharedMemorySize,
                         SM_BYTES);

    k_sq      <<<dim3(NPTS / 256, BSZ), 256>>>(x);
    k_uv      <<<dim3(NPTS / 32,  BSZ), dim3(16, 16)>>>(x, W);
    k_knn     <<<dim3(NPTS / QTILE, BSZ), 256, SM_BYTES>>>(x);
    k_gather  <<<dim3(NPTS / 64,  BSZ), dim3(64, 4)>>>();
    k_finalize<<<1, 64>>>(gamma, beta);
    k_out     <<<dim3(NPTS / 64,  BSZ), dim3(64, 4)>>>(out);
}